// round 1
// baseline (speedup 1.0000x reference)
#include <cuda_runtime.h>
#include <cuda_bf16.h>
#include <math.h>

// RotationalConv2D, GB300 sm_103a
// B=4, H=W=128, C=16, F=32, K=5, stride=1 -> Ho=Wo=124, N=61504 patches = 961*64
//
// One block = 64 consecutive patches; thread (pp, g) with pp=tid>>2, g=tid&3.
// Thread computes out[P][8g .. 8g+7] (8 outputs) over all 400 reduction dims:
//   - intensity/centroid/angle: 4-lane butterfly reduce over channel groups
//   - per target position j: rot[16] by bilinear gather (predicated LDG.128, L1-hot)
//   - FMA against Ws[d][f] held in shared memory (conflict-free LDS.128)

#define HDIM 128
#define WDIM 128
#define CCH 16
#define FOUT 32
#define KK 5
#define HO 124
#define WO 124
#define PPB 64      // patches per block
#define TPB 256

__global__ void __launch_bounds__(TPB, 2)
rotconv_kernel(const float* __restrict__ in,
               const float* __restrict__ Wg,
               const float* __restrict__ bias,
               float* __restrict__ out)
{
    extern __shared__ float Ws[];   // [400][32], d-major, f contiguous

    // --- load W transposed: Ws[d*32+f] = Wg[f*400+d] (write-coalesced) ---
    for (int i = threadIdx.x; i < 400 * 32; i += TPB) {
        int d = i >> 5;
        int f = i & 31;
        Ws[i] = Wg[f * 400 + d];
    }
    __syncthreads();

    const int tid = threadIdx.x;
    const int pp  = tid >> 2;
    const int g   = tid & 3;
    const int P   = blockIdx.x * PPB + pp;

    const int b   = P / (HO * WO);
    int rem       = P - b * (HO * WO);
    const int ho  = rem / WO;
    const int wo  = rem - ho * WO;

    const float* pbase = in + (((b * HDIM + ho) * WDIM + wo) * CCH);

    // --- intensity pass: channel-partial sums over this thread's 4 channels ---
    float tot = 0.f, sr = 0.f, sc = 0.f;
    #pragma unroll
    for (int r = 0; r < KK; r++) {
        #pragma unroll
        for (int cl = 0; cl < KK; cl++) {
            float4 v = *reinterpret_cast<const float4*>(pbase + (r * WDIM + cl) * CCH + g * 4);
            float s = v.x + v.y + v.z + v.w;
            tot += s;
            sr  += s * (float)r;
            sc  += s * (float)cl;
        }
    }
    // butterfly reduce over the 4 g-lanes (lane groups of 4 are aligned)
    tot += __shfl_xor_sync(0xffffffffu, tot, 1);
    tot += __shfl_xor_sync(0xffffffffu, tot, 2);
    sr  += __shfl_xor_sync(0xffffffffu, sr, 1);
    sr  += __shfl_xor_sync(0xffffffffu, sr, 2);
    sc  += __shfl_xor_sync(0xffffffffu, sc, 1);
    sc  += __shfl_xor_sync(0xffffffffu, sc, 2);

    tot += 1e-7f;
    const float cr   = sr / tot;
    const float ccen = sc / tot;
    const float m    = (float)(KK - 1) * 0.5f;           // 2.0
    const float ang  = atan2f(cr - m, ccen - m + 1e-7f);
    const float co   = __cosf(ang);
    const float si   = __sinf(ang);

    const float km1   = (float)(KK - 1);                  // 4.0
    const float xoff  = (km1 - (co * km1 - si * km1)) * 0.5f;
    const float yoff  = (km1 - (si * km1 + co * km1)) * 0.5f;
    const float scale = 1.0f / (1.0f + 1e-7f);

    float pout[8];
    #pragma unroll
    for (int i = 0; i < 8; i++) pout[i] = 0.f;

    // --- main loop over 25 target positions (kept rolled: I$-friendly) ---
    #pragma unroll 1
    for (int jy = 0; jy < KK; jy++) {
        #pragma unroll 1
        for (int jx = 0; jx < KK; jx++) {
            const float gx = (float)jx;
            const float gy = (float)jy;
            const float sx = (co * gx - si * gy + xoff) * scale;
            const float sy = (si * gx + co * gy + yoff) * scale;
            const float x0f = floorf(sx);
            const float y0f = floorf(sy);
            const float wx = sx - x0f;
            const float wy = sy - y0f;
            const int x0 = (int)x0f;
            const int y0 = (int)y0f;

            const float w00 = (1.f - wx) * (1.f - wy);
            const float w01 = wx * (1.f - wy);
            const float w10 = (1.f - wx) * wy;
            const float w11 = wx * wy;
            const float tw[4] = {w00, w01, w10, w11};

            float rot[16];
            #pragma unroll
            for (int c = 0; c < 16; c++) rot[c] = 0.f;

            #pragma unroll
            for (int t = 0; t < 4; t++) {
                const int xi = x0 + (t & 1);
                const int yi = y0 + (t >> 1);
                if (xi >= 0 && xi < KK && yi >= 0 && yi < KK) {
                    const float* tp = pbase + (yi * WDIM + xi) * CCH;
                    const float w = tw[t];
                    #pragma unroll
                    for (int q = 0; q < 4; q++) {
                        float4 v = *reinterpret_cast<const float4*>(tp + q * 4);
                        rot[4 * q + 0] += w * v.x;
                        rot[4 * q + 1] += w * v.y;
                        rot[4 * q + 2] += w * v.z;
                        rot[4 * q + 3] += w * v.w;
                    }
                }
            }

            // --- accumulate into the 8 outputs of this thread's f-slice ---
            const int j = jy * KK + jx;
            const float4* wrow = reinterpret_cast<const float4*>(Ws + j * 16 * 32) + g * 2;
            #pragma unroll
            for (int c = 0; c < 16; c++) {
                const float rv = rot[c];
                const float4 w0 = wrow[c * 8];
                const float4 w1 = wrow[c * 8 + 1];
                pout[0] += rv * w0.x;
                pout[1] += rv * w0.y;
                pout[2] += rv * w0.z;
                pout[3] += rv * w0.w;
                pout[4] += rv * w1.x;
                pout[5] += rv * w1.y;
                pout[6] += rv * w1.z;
                pout[7] += rv * w1.w;
            }
        }
    }

    // --- bias + store (warp covers 8 patches * 128B contiguous) ---
    const float4 b0 = *reinterpret_cast<const float4*>(bias + g * 8);
    const float4 b1 = *reinterpret_cast<const float4*>(bias + g * 8 + 4);
    float* op = out + P * FOUT + g * 8;
    float4 o0, o1;
    o0.x = pout[0] + b0.x; o0.y = pout[1] + b0.y;
    o0.z = pout[2] + b0.z; o0.w = pout[3] + b0.w;
    o1.x = pout[4] + b1.x; o1.y = pout[5] + b1.y;
    o1.z = pout[6] + b1.z; o1.w = pout[7] + b1.w;
    *reinterpret_cast<float4*>(op)     = o0;
    *reinterpret_cast<float4*>(op + 4) = o1;
}

extern "C" void kernel_launch(void* const* d_in, const int* in_sizes, int n_in,
                              void* d_out, int out_size)
{
    const float* in   = (const float*)d_in[0];   // [4,128,128,16]
    const float* Wg   = (const float*)d_in[1];   // [32,5,5,16]
    const float* bias = (const float*)d_in[2];   // [32]
    float* out = (float*)d_out;                  // [4,124,124,32]

    const int smem = 400 * 32 * (int)sizeof(float);   // 51200 B
    cudaFuncSetAttribute(rotconv_kernel,
                         cudaFuncAttributeMaxDynamicSharedMemorySize, smem);

    const int nblocks = (4 * HO * WO) / PPB;          // 961 exactly
    rotconv_kernel<<<nblocks, TPB, smem>>>(in, Wg, bias, out);
}

// round 2
// speedup vs baseline: 2.0151x; 2.0151x over previous
#include <cuda_runtime.h>
#include <cuda_bf16.h>
#include <math.h>

// RotationalConv2D v2 — GB300 sm_103a
// B=4,H=W=128,C=16,F=32,K=5 -> Ho=Wo=124, N=61504 = 961*64
//
// Block: 128 threads, 64 patches. Thread (pp,g): pp=tid>>2 patch-pair
// {base+pp, base+32+pp}, g=tid&3 channel-slice {4g..4g+3}.
// Per j: 4 predicated LDG.128 taps per patch (quad covers all 16 ch with NO
// duplication), partial GEMM over lane's 4 channels into pout[32] per patch
// using Ws2[j][f][c] smem (1 LDS.128 -> 8 FMA). Quad-reduction of the
// channel partials happens ONCE at the end via an smem transpose (reusing
// the W region), not inside the 25-iteration loop.

#define HDIM 128
#define CCH 16
#define FOUT 32
#define KK 5
#define HO 124
#define WO 124
#define TPB 128

__global__ void __launch_bounds__(TPB, 4)
rotconv2_kernel(const float* __restrict__ in,
                const float* __restrict__ Wg,
                const float* __restrict__ bias,
                float* __restrict__ out)
{
    extern __shared__ float sm[];   // phase 1: Ws2[25][32][16]; phase 2: red[64][132]

    // --- stage W as Ws2[j][f][c] ---
    for (int i = threadIdx.x; i < 25 * 32 * 16; i += TPB) {
        int j = i >> 9;          // /512
        int r = i & 511;
        int f = r >> 4;
        int c = r & 15;
        sm[i] = Wg[f * 400 + j * 16 + c];
    }
    __syncthreads();

    const int tid = threadIdx.x;
    const int pp  = tid >> 2;          // 0..31
    const int g   = tid & 3;
    const int base = blockIdx.x * 64;

    const float* pb[2];
    float co[2], si[2], xo[2], yo[2];

    #pragma unroll
    for (int u = 0; u < 2; u++) {
        const int P  = base + u * 32 + pp;
        const int b  = P / (HO * WO);
        const int rem = P - b * (HO * WO);
        const int ho = rem / WO;
        const int wo = rem - ho * WO;
        const float* pbase = in + (((b * HDIM + ho) * HDIM + wo) * CCH);
        pb[u] = pbase;

        // intensity partials over this lane's 4 channels
        float tot = 0.f, sr = 0.f, sc = 0.f;
        #pragma unroll
        for (int r = 0; r < KK; r++) {
            #pragma unroll
            for (int cl = 0; cl < KK; cl++) {
                float4 v = *reinterpret_cast<const float4*>(pbase + (r * HDIM + cl) * CCH + g * 4);
                float s = v.x + v.y + v.z + v.w;
                tot += s;
                sr  += s * (float)r;
                sc  += s * (float)cl;
            }
        }
        tot += __shfl_xor_sync(0xffffffffu, tot, 1);
        tot += __shfl_xor_sync(0xffffffffu, tot, 2);
        sr  += __shfl_xor_sync(0xffffffffu, sr, 1);
        sr  += __shfl_xor_sync(0xffffffffu, sr, 2);
        sc  += __shfl_xor_sync(0xffffffffu, sc, 1);
        sc  += __shfl_xor_sync(0xffffffffu, sc, 2);

        tot += 1e-7f;
        const float cr   = sr / tot;
        const float ccen = sc / tot;
        const float m    = (float)(KK - 1) * 0.5f;
        const float ang  = atan2f(cr - m, ccen - m + 1e-7f);
        const float c_   = __cosf(ang);
        const float s_   = __sinf(ang);
        const float km1  = (float)(KK - 1);
        co[u] = c_;
        si[u] = s_;
        xo[u] = (km1 - (c_ * km1 - s_ * km1)) * 0.5f;
        yo[u] = (km1 - (s_ * km1 + c_ * km1)) * 0.5f;
    }

    const float scale = 1.0f / (1.0f + 1e-7f);

    float pA[FOUT], pB[FOUT];
    #pragma unroll
    for (int f = 0; f < FOUT; f++) { pA[f] = 0.f; pB[f] = 0.f; }

    // --- main loop over 25 target positions ---
    #pragma unroll 1
    for (int jy = 0; jy < KK; jy++) {
        #pragma unroll 1
        for (int jx = 0; jx < KK; jx++) {
            const float gx = (float)jx;
            const float gy = (float)jy;

            float4 rA = make_float4(0.f, 0.f, 0.f, 0.f);
            float4 rB = make_float4(0.f, 0.f, 0.f, 0.f);

            #pragma unroll
            for (int u = 0; u < 2; u++) {
                const float sx = (co[u] * gx - si[u] * gy + xo[u]) * scale;
                const float sy = (si[u] * gx + co[u] * gy + yo[u]) * scale;
                const float x0f = floorf(sx);
                const float y0f = floorf(sy);
                const float wx = sx - x0f;
                const float wy = sy - y0f;
                const int x0 = (int)x0f;
                const int y0 = (int)y0f;
                const float tw[4] = { (1.f - wx) * (1.f - wy),
                                      wx * (1.f - wy),
                                      (1.f - wx) * wy,
                                      wx * wy };
                float4 acc = make_float4(0.f, 0.f, 0.f, 0.f);
                #pragma unroll
                for (int t = 0; t < 4; t++) {
                    const int xi = x0 + (t & 1);
                    const int yi = y0 + (t >> 1);
                    if (xi >= 0 && xi < KK && yi >= 0 && yi < KK) {
                        float4 v = *reinterpret_cast<const float4*>(pb[u] + (yi * HDIM + xi) * CCH + g * 4);
                        const float w = tw[t];
                        acc.x += w * v.x;
                        acc.y += w * v.y;
                        acc.z += w * v.z;
                        acc.w += w * v.w;
                    }
                }
                if (u == 0) rA = acc; else rB = acc;
            }

            // partial GEMM: this lane's 4 channels vs all 32 filters
            const int j = jy * KK + jx;
            const float4* wj = reinterpret_cast<const float4*>(sm) + j * 128 + g;
            #pragma unroll
            for (int f = 0; f < FOUT; f++) {
                const float4 w = wj[f * 4];
                pA[f] += rA.x * w.x + rA.y * w.y + rA.z * w.z + rA.w * w.w;
                pB[f] += rB.x * w.x + rB.y * w.y + rB.z * w.z + rB.w * w.w;
            }
        }
    }

    // --- one-time quad reduction via smem transpose (reuse W region) ---
    __syncthreads();
    float* red = sm;                    // red[p][f*4+g], row stride 132 floats
    #pragma unroll
    for (int f = 0; f < FOUT; f++) red[pp * 132 + f * 4 + g] = pA[f];
    #pragma unroll
    for (int f = 0; f < FOUT; f++) red[(pp + 32) * 132 + f * 4 + g] = pB[f];
    __syncthreads();

    // each thread finalizes 16 outputs: p = tid>>1, f in [16*half, 16*half+16)
    const int p    = tid >> 1;
    const int half = tid & 1;
    const float4* rp = reinterpret_cast<const float4*>(red + p * 132) + half * 16;
    float* op = out + (base + p) * FOUT + half * 16;
    #pragma unroll
    for (int k = 0; k < 4; k++) {
        float4 o;
        float4 v0 = rp[k * 4 + 0];
        float4 v1 = rp[k * 4 + 1];
        float4 v2 = rp[k * 4 + 2];
        float4 v3 = rp[k * 4 + 3];
        const float4 bv = *reinterpret_cast<const float4*>(bias + half * 16 + k * 4);
        o.x = v0.x + v0.y + v0.z + v0.w + bv.x;
        o.y = v1.x + v1.y + v1.z + v1.w + bv.y;
        o.z = v2.x + v2.y + v2.z + v2.w + bv.z;
        o.w = v3.x + v3.y + v3.z + v3.w + bv.w;
        reinterpret_cast<float4*>(op)[k] = o;
    }
}

extern "C" void kernel_launch(void* const* d_in, const int* in_sizes, int n_in,
                              void* d_out, int out_size)
{
    const float* in   = (const float*)d_in[0];   // [4,128,128,16]
    const float* Wg   = (const float*)d_in[1];   // [32,5,5,16]
    const float* bias = (const float*)d_in[2];   // [32]
    float* out = (float*)d_out;                  // [4,124,124,32]

    const int smem = 25 * 32 * 16 * (int)sizeof(float);   // 51200 B (>= 64*132*4 reduce buf)
    cudaFuncSetAttribute(rotconv2_kernel,
                         cudaFuncAttributeMaxDynamicSharedMemorySize, smem);

    const int nblocks = (4 * HO * WO) / 64;               // 961
    rotconv2_kernel<<<nblocks, TPB, smem>>>(in, Wg, bias, out);
}

// round 3
// speedup vs baseline: 2.0422x; 1.0135x over previous
#include <cuda_runtime.h>
#include <cuda_bf16.h>
#include <math.h>

// RotationalConv2D v3 — GB300 sm_103a
// 4 patches/thread, quad channel-split, f32x2 (FFMA2) patch-pair accumulators.
// B=4,H=W=128,C=16,F=32,K=5 -> N=61504 patches; block=128 thr=128 patches; 481 blocks.

#define HDIM 128
#define CCH 16
#define FOUT 32
#define KK 5
#define HO 124
#define WO 124
#define NP (4 * HO * WO)   // 61504
#define TPB 128
#define PPB 128            // patches per block

typedef unsigned long long u64;

__device__ __forceinline__ u64 pk2(float lo, float hi) {
    u64 d; asm("mov.b64 %0, {%1, %2};" : "=l"(d) : "f"(lo), "f"(hi)); return d;
}
__device__ __forceinline__ void upk2(float& lo, float& hi, u64 v) {
    asm("mov.b64 {%0, %1}, %2;" : "=f"(lo), "=f"(hi) : "l"(v));
}
__device__ __forceinline__ u64 ffma2(u64 a, u64 b, u64 c) {
    u64 d; asm("fma.rn.f32x2 %0, %1, %2, %3;" : "=l"(d) : "l"(a), "l"(b), "l"(c)); return d;
}

__global__ void __launch_bounds__(TPB, 2)
rotconv3_kernel(const float* __restrict__ in,
                const float* __restrict__ Wg,
                const float* __restrict__ bias,
                float* __restrict__ out)
{
    extern __shared__ float sm[];   // phase 1: Ws2[25][32][16] (51200B); phase 2: reduce buf

    // --- stage W as Ws2[j][f][c] ---
    for (int i = threadIdx.x; i < 25 * 32 * 16; i += TPB) {
        int j = i >> 9;
        int r = i & 511;
        int f = r >> 4;
        int c = r & 15;
        sm[i] = Wg[f * 400 + j * 16 + c];
    }
    __syncthreads();

    const int tid  = threadIdx.x;
    const int pp   = tid >> 2;      // 0..31
    const int g    = tid & 3;
    const int base = blockIdx.x * PPB;

    int   poff[4];
    float co[4], si[4], xo[4], yo[4];

    #pragma unroll
    for (int u = 0; u < 4; u++) {
        int P = base + pp + 32 * u;
        if (P >= NP) P = NP - 1;                  // tail clamp (stores guarded later)
        const int b   = P / (HO * WO);
        const int rem = P - b * (HO * WO);
        const int ho  = rem / WO;
        const int wo  = rem - ho * WO;
        const int off = ((b * HDIM + ho) * HDIM + wo) * CCH;
        poff[u] = off;
        const float* pbase = in + off;

        float tot = 0.f, sr = 0.f, sc = 0.f;
        #pragma unroll
        for (int r = 0; r < KK; r++) {
            #pragma unroll
            for (int cl = 0; cl < KK; cl++) {
                float4 v = *reinterpret_cast<const float4*>(pbase + (r * HDIM + cl) * CCH + g * 4);
                float s = v.x + v.y + v.z + v.w;
                tot += s;
                sr  += s * (float)r;
                sc  += s * (float)cl;
            }
        }
        tot += __shfl_xor_sync(0xffffffffu, tot, 1);
        tot += __shfl_xor_sync(0xffffffffu, tot, 2);
        sr  += __shfl_xor_sync(0xffffffffu, sr, 1);
        sr  += __shfl_xor_sync(0xffffffffu, sr, 2);
        sc  += __shfl_xor_sync(0xffffffffu, sc, 1);
        sc  += __shfl_xor_sync(0xffffffffu, sc, 2);

        tot += 1e-7f;
        const float cr   = sr / tot;
        const float ccen = sc / tot;
        const float m    = (float)(KK - 1) * 0.5f;
        const float ang  = atan2f(cr - m, ccen - m + 1e-7f);
        const float c_   = __cosf(ang);
        const float s_   = __sinf(ang);
        const float km1  = (float)(KK - 1);
        co[u] = c_;
        si[u] = s_;
        xo[u] = (km1 - (c_ * km1 - s_ * km1)) * 0.5f;
        yo[u] = (km1 - (s_ * km1 + c_ * km1)) * 0.5f;
    }

    const float scale = 1.0f / (1.0f + 1e-7f);

    u64 accAB[FOUT], accCD[FOUT];
    #pragma unroll
    for (int f = 0; f < FOUT; f++) { accAB[f] = 0ull; accCD[f] = 0ull; }

    // --- main loop over 25 target positions ---
    #pragma unroll 1
    for (int jy = 0; jy < KK; jy++) {
        #pragma unroll 1
        for (int jx = 0; jx < KK; jx++) {
            const float gx = (float)jx;
            const float gy = (float)jy;

            float rot[4][4];
            #pragma unroll
            for (int u = 0; u < 4; u++) {
                const float sx  = (co[u] * gx - si[u] * gy + xo[u]) * scale;
                const float sy  = (si[u] * gx + co[u] * gy + yo[u]) * scale;
                const float x0f = floorf(sx);
                const float y0f = floorf(sy);
                const float wx  = sx - x0f;
                const float wy  = sy - y0f;
                const int   x0  = (int)x0f;
                const int   y0  = (int)y0f;
                const float tw[4] = { (1.f - wx) * (1.f - wy),
                                      wx * (1.f - wy),
                                      (1.f - wx) * wy,
                                      wx * wy };
                float a0 = 0.f, a1 = 0.f, a2 = 0.f, a3 = 0.f;
                #pragma unroll
                for (int t = 0; t < 4; t++) {
                    const int xi = x0 + (t & 1);
                    const int yi = y0 + (t >> 1);
                    if (xi >= 0 && xi < KK && yi >= 0 && yi < KK) {
                        const float4 v = *reinterpret_cast<const float4*>(
                            in + poff[u] + (yi * HDIM + xi) * CCH + g * 4);
                        const float w = tw[t];
                        a0 += w * v.x;
                        a1 += w * v.y;
                        a2 += w * v.z;
                        a3 += w * v.w;
                    }
                }
                rot[u][0] = a0; rot[u][1] = a1; rot[u][2] = a2; rot[u][3] = a3;
            }

            // pack rot pairs: (patchA,patchB) and (patchC,patchD) per channel
            u64 rAB[4], rCD[4];
            #pragma unroll
            for (int c = 0; c < 4; c++) {
                rAB[c] = pk2(rot[0][c], rot[1][c]);
                rCD[c] = pk2(rot[2][c], rot[3][c]);
            }

            // GEMM: 1 LDS.128 per f serves 4 patches; FFMA2 = 2 MACs/instr
            const int j = jy * KK + jx;
            const float4* wj = reinterpret_cast<const float4*>(sm) + j * 128 + g;
            #pragma unroll
            for (int f = 0; f < FOUT; f++) {
                const float4 w = wj[f * 4];
                const u64 w0 = pk2(w.x, w.x);
                const u64 w1 = pk2(w.y, w.y);
                const u64 w2 = pk2(w.z, w.z);
                const u64 w3 = pk2(w.w, w.w);
                accAB[f] = ffma2(rAB[0], w0, accAB[f]);
                accCD[f] = ffma2(rCD[0], w0, accCD[f]);
                accAB[f] = ffma2(rAB[1], w1, accAB[f]);
                accCD[f] = ffma2(rCD[1], w1, accCD[f]);
                accAB[f] = ffma2(rAB[2], w2, accAB[f]);
                accCD[f] = ffma2(rCD[2], w2, accCD[f]);
                accAB[f] = ffma2(rAB[3], w3, accAB[f]);
                accCD[f] = ffma2(rCD[3], w3, accCD[f]);
            }
        }
    }

    // --- quad (channel) reduction via smem transpose, two rounds ---
    __syncthreads();
    u64* redu = reinterpret_cast<u64*>(sm);     // [pp][33-padded f][g], 33752B

    #pragma unroll
    for (int round = 0; round < 2; round++) {
        #pragma unroll
        for (int f = 0; f < FOUT; f++)
            redu[(pp * 33 + f) * 4 + g] = (round == 0) ? accAB[f] : accCD[f];
        __syncthreads();

        const int m   = tid >> 1;               // 0..63: patch slot within round
        const int hh  = tid & 1;                // f half
        const int u   = (m >> 5) + round * 2;   // 0..3
        const int ppx = m & 31;
        const int P   = base + ppx + 32 * u;
        if (P < NP) {
            float* op = out + P * FOUT + hh * 16;
            #pragma unroll
            for (int k = 0; k < 16; k += 4) {
                float4 o;
                float res[4];
                #pragma unroll
                for (int q = 0; q < 4; q++) {
                    const int f = hh * 16 + k + q;
                    float s = 0.f;
                    #pragma unroll
                    for (int gg = 0; gg < 4; gg++) {
                        float lo, hi;
                        upk2(lo, hi, redu[(ppx * 33 + f) * 4 + gg]);
                        s += (m < 32) ? lo : hi;
                    }
                    res[q] = s + __ldg(bias + f);
                }
                o.x = res[0]; o.y = res[1]; o.z = res[2]; o.w = res[3];
                *reinterpret_cast<float4*>(op + k) = o;
            }
        }
        __syncthreads();
    }
}

extern "C" void kernel_launch(void* const* d_in, const int* in_sizes, int n_in,
                              void* d_out, int out_size)
{
    const float* in   = (const float*)d_in[0];   // [4,128,128,16]
    const float* Wg   = (const float*)d_in[1];   // [32,5,5,16]
    const float* bias = (const float*)d_in[2];   // [32]
    float* out = (float*)d_out;                  // [4,124,124,32]

    const int smem = 25 * 32 * 16 * (int)sizeof(float);   // 51200 B
    cudaFuncSetAttribute(rotconv3_kernel,
                         cudaFuncAttributeMaxDynamicSharedMemorySize, smem);

    const int nblocks = (NP + PPB - 1) / PPB;             // 481
    rotconv3_kernel<<<nblocks, TPB, smem>>>(in, Wg, bias, out);
}